// round 1
// baseline (speedup 1.0000x reference)
#include <cuda_runtime.h>
#include <cuda_bf16.h>

// Comparator4Bit: A,B are (N,4) float32 with values in {0,1}.
// col0 = bit3 (MSB) ... col3 = bit0 (LSB).
// a_gt_b = (valA > valB), a_eq_b = (valA == valB), both as float32.
// Output: out[0:N] = a_gt_b, out[N:2N] = a_eq_b.
//
// Pure HBM-bound: 128 MiB read + 32 MiB write. One thread handles 4 rows:
// 8x LDG.128 + 2x STG.128, fully coalesced.

static __device__ __forceinline__ int pack_row(const float4 v) {
    // values are exactly 0.0f or 1.0f
    return (int(v.x) << 3) | (int(v.y) << 2) | (int(v.z) << 1) | int(v.w);
}

__global__ void __launch_bounds__(256)
comparator4bit_kernel(const float4* __restrict__ A4,
                      const float4* __restrict__ B4,
                      float* __restrict__ out_gt,
                      float* __restrict__ out_eq,
                      int n_rows)   // total rows N (multiple of 4)
{
    // Each thread handles 4 consecutive rows.
    int t = blockIdx.x * blockDim.x + threadIdx.x;
    int base = t * 4;
    if (base >= n_rows) return;

    // Front-batch all 8 loads for max MLP.
    float4 a0 = A4[base + 0];
    float4 a1 = A4[base + 1];
    float4 a2 = A4[base + 2];
    float4 a3 = A4[base + 3];
    float4 b0 = B4[base + 0];
    float4 b1 = B4[base + 1];
    float4 b2 = B4[base + 2];
    float4 b3 = B4[base + 3];

    int va0 = pack_row(a0), vb0 = pack_row(b0);
    int va1 = pack_row(a1), vb1 = pack_row(b1);
    int va2 = pack_row(a2), vb2 = pack_row(b2);
    int va3 = pack_row(a3), vb3 = pack_row(b3);

    float4 gt, eq;
    gt.x = (va0 > vb0) ? 1.0f : 0.0f;  eq.x = (va0 == vb0) ? 1.0f : 0.0f;
    gt.y = (va1 > vb1) ? 1.0f : 0.0f;  eq.y = (va1 == vb1) ? 1.0f : 0.0f;
    gt.z = (va2 > vb2) ? 1.0f : 0.0f;  eq.z = (va2 == vb2) ? 1.0f : 0.0f;
    gt.w = (va3 > vb3) ? 1.0f : 0.0f;  eq.w = (va3 == vb3) ? 1.0f : 0.0f;

    reinterpret_cast<float4*>(out_gt)[t] = gt;
    reinterpret_cast<float4*>(out_eq)[t] = eq;
}

extern "C" void kernel_launch(void* const* d_in, const int* in_sizes, int n_in,
                              void* d_out, int out_size) {
    const float* A = (const float*)d_in[0];
    const float* B = (const float*)d_in[1];
    float* out = (float*)d_out;

    int n_rows = in_sizes[0] / 4;   // (N,4) float32 -> N rows
    float* out_gt = out;            // [0:N)
    float* out_eq = out + n_rows;   // [N:2N)

    int threads = 256;
    int rows_per_thread = 4;
    int total_threads = n_rows / rows_per_thread;
    int blocks = (total_threads + threads - 1) / threads;

    comparator4bit_kernel<<<blocks, threads>>>(
        (const float4*)A, (const float4*)B, out_gt, out_eq, n_rows);
}